// round 1
// baseline (speedup 1.0000x reference)
#include <cuda_runtime.h>

// Problem constants
#define BB   2
#define SS   1024
#define DD   2048
#define QH   32
#define KH   8
#define HD   64
#define MTOT (BB*SS)        // 2048 rows

// ---------------- scratch (device globals: allocation-free) ----------------
__device__ float g_Qp[MTOT * DD];          // [b*s][qh*hd]  = [2048][2048]
__device__ float g_Kp[MTOT * KH * HD];     // [2048][512]
__device__ float g_Vp[MTOT * KH * HD];     // [2048][512]
__device__ float g_Ao[MTOT * DD];          // attention out, [2048][2048]

// ---------------- generic 128x128 SGEMM, K-step 16 ----------------
// C[M,N] = A[M,K] @ W[K,N] + bias[N].  blockIdx.z selects (W0,b0,C0) vs (W1,b1,C1)
// Requires M%128==0, N%128==0, K%16==0 (true for all uses here).
#define TS 128
#define KS 16

__global__ __launch_bounds__(256, 2)
void sgemm128(const float* __restrict__ A,
              const float* __restrict__ W0, const float* __restrict__ b0, float* __restrict__ C0,
              const float* __restrict__ W1, const float* __restrict__ b1, float* __restrict__ C1,
              int M, int N, int K)
{
    const float* W    = blockIdx.z ? W1 : W0;
    const float* bias = blockIdx.z ? b1 : b0;
    float*       C    = blockIdx.z ? C1 : C0;

    __shared__ float As[KS][TS];   // A tile, transposed: As[k][m]
    __shared__ float Bs[KS][TS];   // W tile, natural:    Bs[k][n]

    const int tid = threadIdx.x;
    const int tx = tid & 15, ty = tid >> 4;
    const int row0 = blockIdx.y * TS;
    const int col0 = blockIdx.x * TS;

    float acc[8][8];
#pragma unroll
    for (int i = 0; i < 8; i++)
#pragma unroll
        for (int j = 0; j < 8; j++) acc[i][j] = 0.f;

    // A-load mapping: 128 rows x 16 k, 2 passes of 64 rows
    const int ar = tid >> 2;          // 0..63
    const int ak = (tid & 3) * 4;     // 0,4,8,12
    // B-load mapping: 16 rows x 128 cols, 2 passes of 8 rows
    const int br = tid >> 5;          // 0..7
    const int bc = (tid & 31) * 4;    // 0..124

    for (int kt = 0; kt < K; kt += KS) {
#pragma unroll
        for (int it = 0; it < 2; it++) {
            int r = ar + it * 64;
            float4 v = *(const float4*)&A[(size_t)(row0 + r) * K + kt + ak];
            As[ak + 0][r] = v.x; As[ak + 1][r] = v.y;
            As[ak + 2][r] = v.z; As[ak + 3][r] = v.w;
        }
#pragma unroll
        for (int it = 0; it < 2; it++) {
            int r = br + it * 8;
            *(float4*)&Bs[r][bc] = *(const float4*)&W[(size_t)(kt + r) * N + col0 + bc];
        }
        __syncthreads();

#pragma unroll
        for (int kk = 0; kk < KS; kk++) {
            float4 a0 = *(float4*)&As[kk][ty * 4];
            float4 a1 = *(float4*)&As[kk][64 + ty * 4];
            float4 c0 = *(float4*)&Bs[kk][tx * 4];
            float4 c1 = *(float4*)&Bs[kk][64 + tx * 4];
            float a[8] = {a0.x, a0.y, a0.z, a0.w, a1.x, a1.y, a1.z, a1.w};
            float b[8] = {c0.x, c0.y, c0.z, c0.w, c1.x, c1.y, c1.z, c1.w};
#pragma unroll
            for (int i = 0; i < 8; i++)
#pragma unroll
                for (int j = 0; j < 8; j++)
                    acc[i][j] += a[i] * b[j];
        }
        __syncthreads();
    }

    // epilogue
    const int cc0 = col0 + tx * 4;
    const int cc1 = col0 + 64 + tx * 4;
    float4 bv0 = *(const float4*)&bias[cc0];
    float4 bv1 = *(const float4*)&bias[cc1];
#pragma unroll
    for (int i = 0; i < 8; i++) {
        int r = row0 + ((i < 4) ? (ty * 4 + i) : (64 + ty * 4 + i - 4));
        float4 o0 = make_float4(acc[i][0] + bv0.x, acc[i][1] + bv0.y,
                                acc[i][2] + bv0.z, acc[i][3] + bv0.w);
        float4 o1 = make_float4(acc[i][4] + bv1.x, acc[i][5] + bv1.y,
                                acc[i][6] + bv1.z, acc[i][7] + bv1.w);
        *(float4*)&C[(size_t)r * N + cc0] = o0;
        *(float4*)&C[(size_t)r * N + cc1] = o1;
    }
}

// ---------------- causal GQA flash attention ----------------
// grid: (16 q-tiles, B*QH), block: 256 threads.
// Each block: 64 q-rows x full head-dim 64. K/V tiles of 64 rows, online softmax.
#define STR 68   // smem row stride (floats); mult of 4 for float4 alignment

__global__ __launch_bounds__(256, 3)
void attn_kernel(const float* __restrict__ Qp, const float* __restrict__ Kp,
                 const float* __restrict__ Vp, float* __restrict__ Ao)
{
    extern __shared__ float sm[];
    float* sQ  = sm;                 // [64][STR]  row-major (r, d)
    float* sKT = sQ  + 64 * STR;     // [64][STR]  TRANSPOSED (d, kcol)
    float* sV  = sKT + 64 * STR;     // [64][STR]  row-major (kcol, d)
    float* sP  = sV  + 64 * STR;     // [64][STR]  (qrow, kcol)

    const int bh = blockIdx.y;
    const int b  = bh >> 5;
    const int h  = bh & 31;
    const int kh = h >> 2;          // REP = 4
    const int y  = blockIdx.x;      // q tile index (0..15)
    const int tid = threadIdx.x;
    const int tx = tid & 15, ty = tid >> 4;

    const float* qbase = Qp + ((size_t)(b * SS + y * 64)) * DD + h * HD;
    const float* kbase = Kp + ((size_t)(b * SS)) * (KH * HD) + kh * HD;
    const float* vbase = Vp + ((size_t)(b * SS)) * (KH * HD) + kh * HD;

    // load Q tile, pre-scaled by 1/sqrt(64)
    for (int f = tid; f < 1024; f += 256) {
        int r = f >> 4, c4 = (f & 15) * 4;
        float4 v = *(const float4*)&qbase[(size_t)r * DD + c4];
        v.x *= 0.125f; v.y *= 0.125f; v.z *= 0.125f; v.w *= 0.125f;
        *(float4*)&sQ[r * STR + c4] = v;
    }

    float acc[4][4];
#pragma unroll
    for (int i = 0; i < 4; i++)
#pragma unroll
        for (int j = 0; j < 4; j++) acc[i][j] = 0.f;
    float m_r[4], l_r[4];
#pragma unroll
    for (int i = 0; i < 4; i++) { m_r[i] = -1e30f; l_r[i] = 0.f; }

    for (int j = 0; j <= y; j++) {
        // load K (transposed) and V tiles
        for (int f = tid; f < 1024; f += 256) {
            int r = f >> 4, c4 = (f & 15) * 4;
            float4 kv4 = *(const float4*)&kbase[(size_t)(j * 64 + r) * (KH * HD) + c4];
            sKT[(c4 + 0) * STR + r] = kv4.x;
            sKT[(c4 + 1) * STR + r] = kv4.y;
            sKT[(c4 + 2) * STR + r] = kv4.z;
            sKT[(c4 + 3) * STR + r] = kv4.w;
            float4 vv4 = *(const float4*)&vbase[(size_t)(j * 64 + r) * (KH * HD) + c4];
            *(float4*)&sV[r * STR + c4] = vv4;
        }
        __syncthreads();   // covers sQ on first iteration too

        // scores s[i][jj] = (Q/8) . K for rows ty*4+i, cols tx*4+jj
        float s[4][4];
#pragma unroll
        for (int i = 0; i < 4; i++)
#pragma unroll
            for (int jj = 0; jj < 4; jj++) s[i][jj] = 0.f;
#pragma unroll 8
        for (int d = 0; d < 64; d++) {
            float4 k4 = *(float4*)&sKT[d * STR + tx * 4];
#pragma unroll
            for (int i = 0; i < 4; i++) {
                float qv = sQ[(ty * 4 + i) * STR + d];
                s[i][0] += qv * k4.x; s[i][1] += qv * k4.y;
                s[i][2] += qv * k4.z; s[i][3] += qv * k4.w;
            }
        }

        if (j == y) {
#pragma unroll
            for (int i = 0; i < 4; i++)
#pragma unroll
                for (int jj = 0; jj < 4; jj++)
                    if (tx * 4 + jj > ty * 4 + i) s[i][jj] = -1e30f;
        }

        // online softmax update (reductions within 16-lane tx groups)
#pragma unroll
        for (int i = 0; i < 4; i++) {
            float rmax = fmaxf(fmaxf(s[i][0], s[i][1]), fmaxf(s[i][2], s[i][3]));
#pragma unroll
            for (int o = 8; o >= 1; o >>= 1)
                rmax = fmaxf(rmax, __shfl_xor_sync(0xffffffffu, rmax, o));
            float mn    = fmaxf(m_r[i], rmax);
            float alpha = __expf(m_r[i] - mn);
            m_r[i] = mn;
            float rs = 0.f;
#pragma unroll
            for (int jj = 0; jj < 4; jj++) {
                float p = __expf(s[i][jj] - mn);
                sP[(ty * 4 + i) * STR + tx * 4 + jj] = p;
                rs += p;
            }
#pragma unroll
            for (int o = 8; o >= 1; o >>= 1)
                rs += __shfl_xor_sync(0xffffffffu, rs, o);
            l_r[i] = l_r[i] * alpha + rs;
#pragma unroll
            for (int jj = 0; jj < 4; jj++) acc[i][jj] *= alpha;
        }
        __syncthreads();   // sP visible

        // acc += P @ V  (rows ty*4+i, d-cols tx*4..+3)
#pragma unroll 8
        for (int k = 0; k < 64; k++) {
            float4 vv = *(float4*)&sV[k * STR + tx * 4];
#pragma unroll
            for (int i = 0; i < 4; i++) {
                float pv = sP[(ty * 4 + i) * STR + k];
                acc[i][0] += pv * vv.x; acc[i][1] += pv * vv.y;
                acc[i][2] += pv * vv.z; acc[i][3] += pv * vv.w;
            }
        }
        __syncthreads();   // before next tile overwrites sKT/sV
    }

    // normalize + write: Ao[b, qrow, h*64 + d]
#pragma unroll
    for (int i = 0; i < 4; i++) {
        int qg = y * 64 + ty * 4 + i;
        float inv = 1.f / l_r[i];
        float4 o = make_float4(acc[i][0] * inv, acc[i][1] * inv,
                               acc[i][2] * inv, acc[i][3] * inv);
        *(float4*)&Ao[((size_t)(b * SS + qg)) * DD + h * HD + tx * 4] = o;
    }
}

#define ATTN_SMEM (4 * 64 * STR * sizeof(float))   // 69,632 B

// ---------------- launcher ----------------
extern "C" void kernel_launch(void* const* d_in, const int* in_sizes, int n_in,
                              void* d_out, int out_size)
{
    const float* q  = (const float*)d_in[0];
    const float* kv = (const float*)d_in[1];
    // d_in[2] = mask (causal, known statically) -- unused
    const float* Wq = (const float*)d_in[3];
    const float* bq = (const float*)d_in[4];
    const float* Wk = (const float*)d_in[5];
    const float* bk = (const float*)d_in[6];
    const float* Wv = (const float*)d_in[7];
    const float* bv = (const float*)d_in[8];
    const float* Wo = (const float*)d_in[9];
    const float* bo = (const float*)d_in[10];
    float* out = (float*)d_out;

    float *Qp, *Kp, *Vp, *Ao;
    cudaGetSymbolAddress((void**)&Qp, g_Qp);
    cudaGetSymbolAddress((void**)&Kp, g_Kp);
    cudaGetSymbolAddress((void**)&Vp, g_Vp);
    cudaGetSymbolAddress((void**)&Ao, g_Ao);

    cudaFuncSetAttribute(attn_kernel,
                         cudaFuncAttributeMaxDynamicSharedMemorySize, (int)ATTN_SMEM);

    // 1) Q projection: [2048,2048] = q @ Wq
    sgemm128<<<dim3(DD / TS, MTOT / TS, 1), 256>>>(
        q, Wq, bq, Qp, Wq, bq, Qp, MTOT, DD, DD);

    // 2) K and V projections fused via gridDim.z: [2048,512]
    sgemm128<<<dim3((KH * HD) / TS, MTOT / TS, 2), 256>>>(
        kv, Wk, bk, Kp, Wv, bv, Vp, MTOT, KH * HD, DD);

    // 3) causal GQA attention -> Ao [2048, 2048]
    attn_kernel<<<dim3(SS / 64, BB * QH), 256, ATTN_SMEM>>>(Qp, Kp, Vp, Ao);

    // 4) output projection: out = Ao @ Wo + bo
    sgemm128<<<dim3(DD / TS, MTOT / TS, 1), 256>>>(
        Ao, Wo, bo, out, Wo, bo, out, MTOT, DD, DD);
}